// round 8
// baseline (speedup 1.0000x reference)
#include <cuda_runtime.h>
#include <stdint.h>

// Fixed shapes
constexpr int Bn = 4096;
constexpr int Tn = 8192;
constexpr int Dn = 1024;
constexpr int FS = 21;
constexpr int PAD = 10;        // FILTER_SIZE // 2
constexpr int NT  = 512;       // threads per block
constexpr int NW  = NT / 32;   // 16 warps
constexpr int GRID = 304;      // 2 CTAs/SM on 152 SMs; work stealing absorbs mismatch
constexpr int CHUNK = Tn / 4;  // 2048 outputs per chunk
constexpr float MIN_SIGMA_C  = 0.2f;
constexpr float MASK_VALUE_C = 1e-8f;

// Dynamic SMEM layout (float indices)
constexpr int BUFSZ   = 8224;             // aw buffer: data at [PAD, PAD+Tn), halos zeroed once
constexpr int OFF_OB  = 2 * BUFSZ;        // conv output staging: 8192 (no halo)
constexpr int OFF_Q   = OFF_OB + Tn;      // query row: 1024
constexpr int OFF_DOT = OFF_Q + 1024;     // 4 x NW = 64
constexpr int OFF_KER = OFF_DOT + 64;     // 21 (pad 24)
constexpr int OFF_RED = OFF_KER + 24;     // NW
constexpr int OFF_SCL = OFF_RED + NW;     // 1 (row total), padded
constexpr int OFF_B   = OFF_SCL + 2;      // 1 int (claimed row), padded
constexpr int SM_FLOATS = OFF_B + 2;
constexpr int SM_BYTES  = SM_FLOATS * 4;  // ~103 KB; 2 CTAs/SM = ~206 KB <= 228 KB

__device__ int g_ctr;

__global__ void reset_ctr_kernel() { g_ctr = 0; }

__device__ __forceinline__ void cp8(uint32_t dst, const float* src) {
    asm volatile("cp.async.ca.shared.global [%0], [%1], 8;" :: "r"(dst), "l"(src));
}
__device__ __forceinline__ void cp_commit()  { asm volatile("cp.async.commit_group;"); }
__device__ __forceinline__ void cp_wait_all(){ asm volatile("cp.async.wait_group 0;"); }

// Persistent CTAs; rows claimed by atomicAdd. Row k+1's aw+query stream in via
// cp.async during row k's conv. Conv writes go to a SEPARATE staging buffer
// (obuf) so the 4 conv chunks need NO barriers (R7 post-mortem: 4 in-loop
// __syncthreads serialized 16 warps; nothing was saturated). aw-buffer halos
// are zeroed once and never corrupted. proj_w read straight from L2 (16KB/row
// of pure hits). Mask is marshalled as int32 (proven in R1: rel_err == sqrt(3)).
__global__ __launch_bounds__(NT, 2)
void gauss_attn_kernel(const float* __restrict__ query,
                       const float* __restrict__ aw,
                       const int* __restrict__ mask,
                       const float* __restrict__ proj_w,
                       const float* __restrict__ proj_b,
                       float* __restrict__ out)
{
    extern __shared__ float sm[];
    int* smi = (int*)sm;
    const uint32_t smBase = (uint32_t)__cvta_generic_to_shared(sm);

    const int tid  = threadIdx.x;
    const int lane = tid & 31;
    const int wrp  = tid >> 5;

    // proj bias cached in a register (meaningful only in warp 0, lanes 0-3)
    float pbias = 0.0f;
    if (wrp == 0 && lane < 4) pbias = proj_b[lane];

    // ---------- prologue: claim first row, zero halos (once — never rewritten) ----------
    if (tid == 0) smi[OFF_B] = atomicAdd(&g_ctr, 1);
    if (tid < PAD) { sm[tid] = 0.0f; sm[BUFSZ + tid] = 0.0f; }
    if (tid < 22)  { sm[PAD + Tn + tid] = 0.0f; sm[BUFSZ + PAD + Tn + tid] = 0.0f; }
    __syncthreads();
    int b = smi[OFF_B];
    if (b >= Bn) return;                       // whole CTA exits together

    {   // prefetch aw row b + query row b into SMEM
        const float* aw0 = aw + (size_t)b * Tn;
        #pragma unroll
        for (int k = 0; k < 8; k++) {
            int u = k * NT + tid;
            cp8(smBase + 4u * (uint32_t)(PAD + 2 * u), aw0 + 2 * u);
        }
        cp8(smBase + 4u * (uint32_t)(OFF_Q + 2 * tid), query + (size_t)b * Dn + 2 * tid);
        cp_commit();
    }

    int pbuf = 0;
    while (b < Bn) {
        float* buf = sm + pbuf * BUFSZ;
        const int nbo = (pbuf ^ 1) * BUFSZ;

        cp_wait_all();          // aw(b), query(b) resident
        __syncthreads();

        if (tid == 0) smi[OFF_B] = atomicAdd(&g_ctr, 1);   // claim next row

        // ---------- projection dots (query from SMEM, proj_w from L2) ----------
        {
            float q0 = sm[OFF_Q + tid];
            float q1 = sm[OFF_Q + NT + tid];
            float d0 = q0 * proj_w[0 * Dn + tid] + q1 * proj_w[0 * Dn + tid + NT];
            float d1 = q0 * proj_w[1 * Dn + tid] + q1 * proj_w[1 * Dn + tid + NT];
            float d2 = q0 * proj_w[2 * Dn + tid] + q1 * proj_w[2 * Dn + tid + NT];
            float d3 = q0 * proj_w[3 * Dn + tid] + q1 * proj_w[3 * Dn + tid + NT];
            #pragma unroll
            for (int o = 16; o; o >>= 1) {
                d0 += __shfl_xor_sync(0xffffffffu, d0, o);
                d1 += __shfl_xor_sync(0xffffffffu, d1, o);
                d2 += __shfl_xor_sync(0xffffffffu, d2, o);
                d3 += __shfl_xor_sync(0xffffffffu, d3, o);
            }
            if (lane == 0) {
                sm[OFF_DOT + 0 * NW + wrp] = d0;
                sm[OFF_DOT + 1 * NW + wrp] = d1;
                sm[OFF_DOT + 2 * NW + wrp] = d2;
                sm[OFF_DOT + 3 * NW + wrp] = d3;
            }
        }
        __syncthreads();
        const int bn = smi[OFF_B];

        // ---------- warp 0: sigmoid -> 21-tap normalized kernel ----------
        if (wrp == 0) {
            float sv = 0.0f;
            if (lane < 4) {
                #pragma unroll
                for (int i = 0; i < NW; i++) sv += sm[OFF_DOT + lane * NW + i];
                sv += pbias;
                sv = 1.0f / (1.0f + expf(-sv));
            }
            float p0 = __shfl_sync(0xffffffffu, sv, 0);
            float p1 = __shfl_sync(0xffffffffu, sv, 1);
            float p2 = __shfl_sync(0xffffffffu, sv, 2);
            float p3 = __shfl_sync(0xffffffffu, sv, 3);
            float mu  = (float)PAD - p0 * 2.0f;   // 2 * PRIOR_TOKENS_PER_FRAME
            float sg0 = MIN_SIGMA_C + p2;
            float sg1 = sg0 + p3;
            float kv = 0.0f;
            if (lane < FS) {
                float kk = (float)lane;
                float z0 = (kk - mu) / (2.0f * sg0);
                float z1 = (kk - mu) / (2.0f * sg1);
                kv = (1.0f + p1) * (expf(-z0 * z0) / sg0) - p1 * (expf(-z1 * z1) / sg1);
            }
            float ks = kv;
            #pragma unroll
            for (int o = 16; o; o >>= 1) ks += __shfl_xor_sync(0xffffffffu, ks, o);
            if (lane < FS) sm[OFF_KER + lane] = kv / ks;
        }
        __syncthreads();                        // kr visible to all warps

        float kr[FS];
        #pragma unroll
        for (int i = 0; i < FS; i++) kr[i] = sm[OFF_KER + i];   // broadcast LDS

        // ---------- conv + mask + clip: 4 chunks, NO barriers ----------
        const bool  pf  = (bn < Bn);
        const float* awn = aw + (size_t)bn * Tn;
        const float* qn  = query + (size_t)bn * Dn;
        const int4*  mrow = (const int4*)(mask + (size_t)b * Tn);
        float lsum = 0.0f;

        #pragma unroll
        for (int c = 0; c < 4; c++) {
            const int t0 = c * CHUNK + tid * 4;

            if (pf) {                           // 2 x 8B aw units + (chunk0) query
                int u = c * (2 * NT) + tid;
                cp8(smBase + 4u * (uint32_t)(nbo + PAD + 2 * u),        awn + 2 * u);
                cp8(smBase + 4u * (uint32_t)(nbo + PAD + 2 * (u + NT)), awn + 2 * (u + NT));
                if (c == 0)
                    cp8(smBase + 4u * (uint32_t)(OFF_Q + 2 * tid), qn + 2 * tid);
                cp_commit();
            }

            int4 mm = mrow[t0 >> 2];            // mask marshalled as int32

            float w[24];
            #pragma unroll
            for (int j = 0; j < 6; j++) {
                float4 vv = *(const float4*)(&buf[t0 + 4 * j]);
                w[4 * j + 0] = vv.x; w[4 * j + 1] = vv.y;
                w[4 * j + 2] = vv.z; w[4 * j + 3] = vv.w;
            }

            float v[4];
            #pragma unroll
            for (int rr = 0; rr < 4; rr++) {
                float acc = 0.0f;
                #pragma unroll
                for (int i = 0; i < FS; i++) acc = fmaf(w[rr + i], kr[i], acc);
                v[rr] = acc;
            }

            v[0] = fmaxf(mm.x ? v[0] : MASK_VALUE_C, MASK_VALUE_C);
            v[1] = fmaxf(mm.y ? v[1] : MASK_VALUE_C, MASK_VALUE_C);
            v[2] = fmaxf(mm.z ? v[2] : MASK_VALUE_C, MASK_VALUE_C);
            v[3] = fmaxf(mm.w ? v[3] : MASK_VALUE_C, MASK_VALUE_C);
            lsum += v[0] + v[1] + v[2] + v[3];

            // staging buffer: disjoint from all conv reads -> no barrier needed
            *(float4*)(&sm[OFF_OB + t0]) = make_float4(v[0], v[1], v[2], v[3]);
        }

        // ---------- block-reduce the row sum ----------
        #pragma unroll
        for (int o = 16; o; o >>= 1) lsum += __shfl_xor_sync(0xffffffffu, lsum, o);
        if (lane == 0) sm[OFF_RED + wrp] = lsum;
        __syncthreads();                         // also orders obuf STS before LDS below
        if (wrp == 0) {                          // all 32 lanes participate
            float s = (lane < NW) ? sm[OFF_RED + lane] : 0.0f;
            #pragma unroll
            for (int o = 16; o; o >>= 1) s += __shfl_xor_sync(0xffffffffu, s, o);
            if (lane == 0) sm[OFF_SCL] = s;
        }
        __syncthreads();

        // ---------- normalize + coalesced vector store ----------
        const float rinv = 1.0f / sm[OFF_SCL];
        float4* outv = (float4*)(out + (size_t)b * Tn);
        #pragma unroll
        for (int c = 0; c < 4; c++) {
            float4 vv = *(const float4*)(&sm[OFF_OB + 4 * (tid + c * NT)]);
            vv.x *= rinv; vv.y *= rinv; vv.z *= rinv; vv.w *= rinv;
            outv[tid + c * NT] = vv;
        }

        b = bn;
        pbuf ^= 1;
        // next iteration's top cp_wait + __syncthreads fences buffer reuse
    }
}

extern "C" void kernel_launch(void* const* d_in, const int* in_sizes, int n_in,
                              void* d_out, int out_size)
{
    const float* query  = (const float*)d_in[0];
    const float* aw     = (const float*)d_in[1];
    const int*   mask   = (const int*)d_in[2];
    const float* proj_w = (const float*)d_in[3];
    const float* proj_b = (const float*)d_in[4];
    float*       out    = (float*)d_out;

    cudaFuncSetAttribute(gauss_attn_kernel,
                         cudaFuncAttributeMaxDynamicSharedMemorySize, SM_BYTES);
    reset_ctr_kernel<<<1, 1>>>();
    gauss_attn_kernel<<<GRID, NT, SM_BYTES>>>(query, aw, mask, proj_w, proj_b, out);
}

// round 10
// speedup vs baseline: 1.1218x; 1.1218x over previous
#include <cuda_runtime.h>
#include <stdint.h>

// Fixed shapes
constexpr int Bn = 4096;
constexpr int Tn = 8192;
constexpr int Dn = 1024;
constexpr int FS = 21;
constexpr int PAD = 10;        // FILTER_SIZE // 2
constexpr int NT  = 512;       // threads per block
constexpr int NW  = NT / 32;   // 16 warps
constexpr int GRID = 304;      // 2 CTAs/SM; work stealing absorbs mismatch
constexpr int CHUNK = Tn / 4;  // 2048 outputs per chunk
constexpr float MIN_SIGMA_C  = 0.2f;
constexpr float MASK_VALUE_C = 1e-8f;

// Dynamic SMEM layout (float indices) — ~66 KB/CTA, preserves L1D carveout (R8 lesson)
constexpr int BUFSZ   = 8224;             // aw buffer: data at [PAD, PAD+Tn), halos zeroed
constexpr int OFF_DOT = 2 * BUFSZ;        // 4 x NW = 64
constexpr int OFF_KER = OFF_DOT + 64;     // 21 (pad 24)
constexpr int OFF_RED = OFF_KER + 24;     // NW
constexpr int OFF_SCL = OFF_RED + NW;     // 1 (row total), padded
constexpr int OFF_B   = OFF_SCL + 2;      // 1 int (claimed row), padded
constexpr int SM_FLOATS = OFF_B + 2;
constexpr int SM_BYTES  = SM_FLOATS * 4;

__device__ int g_ctr;

__global__ void reset_ctr_kernel() { g_ctr = 0; }

__device__ __forceinline__ void cp8(uint32_t dst, const float* src) {
    asm volatile("cp.async.ca.shared.global [%0], [%1], 8;" :: "r"(dst), "l"(src));
}
__device__ __forceinline__ void cp_commit()  { asm volatile("cp.async.commit_group;"); }
__device__ __forceinline__ void cp_wait_all(){ asm volatile("cp.async.wait_group 0;"); }

// Persistent CTAs, rows via atomicAdd. Pipeline per row:
//  - prev row's normalize+store issued as ONE burst right after loop-top sync
//    (STG is fire-and-forget; drains async under the following conv). All pbv
//    reads finish before the post-ker barrier -> conv chunk c prefetches
//    region c of aw(next) into pbv with zero overlap (R9 race eliminated:
//    that version prefetched region c-1 during chunk c, whose PAD-shifted
//    tail overlapped chunk c's deferred-store reads).
//  - kernel-build for row b uses dots staged during the previous row's conv;
//    conv chunk 0 computes next row's dots (L2-hot LDGs hide under conv).
//  - in-place conv trick: v[t] -> buf[t] (shift -PAD), pre-write barrier/chunk.
// Mask is marshalled as int32 (proven in R1: rel_err == sqrt(3)).
__global__ __launch_bounds__(NT, 2)
void gauss_attn_kernel(const float* __restrict__ query,
                       const float* __restrict__ aw,
                       const int* __restrict__ mask,
                       const float* __restrict__ proj_w,
                       const float* __restrict__ proj_b,
                       float* __restrict__ out)
{
    extern __shared__ float sm[];
    int* smi = (int*)sm;
    const uint32_t smBase = (uint32_t)__cvta_generic_to_shared(sm);

    const int tid  = threadIdx.x;
    const int lane = tid & 31;
    const int wrp  = tid >> 5;

    float pbias = 0.0f;                       // warp 0 lanes 0-3 only
    if (wrp == 0 && lane < 4) pbias = proj_b[lane];

    // ---------- prologue ----------
    if (tid == 0) smi[OFF_B] = atomicAdd(&g_ctr, 1);
    if (tid < PAD) { sm[tid] = 0.0f; sm[BUFSZ + tid] = 0.0f; }
    if (tid < 22)  { sm[PAD + Tn + tid] = 0.0f; sm[BUFSZ + PAD + Tn + tid] = 0.0f; }
    __syncthreads();
    int b = smi[OFF_B];
    if (b >= Bn) return;                      // whole CTA exits together

    {   // prefetch aw(b) into buf0; compute dots(b) directly
        const float* aw0 = aw + (size_t)b * Tn;
        #pragma unroll
        for (int k = 0; k < 8; k++) {
            int u = k * NT + tid;
            cp8(smBase + 4u * (uint32_t)(PAD + 2 * u), aw0 + 2 * u);
        }
        cp_commit();

        float q0 = query[(size_t)b * Dn + tid];
        float q1 = query[(size_t)b * Dn + tid + NT];
        float d0 = q0 * proj_w[0 * Dn + tid] + q1 * proj_w[0 * Dn + tid + NT];
        float d1 = q0 * proj_w[1 * Dn + tid] + q1 * proj_w[1 * Dn + tid + NT];
        float d2 = q0 * proj_w[2 * Dn + tid] + q1 * proj_w[2 * Dn + tid + NT];
        float d3 = q0 * proj_w[3 * Dn + tid] + q1 * proj_w[3 * Dn + tid + NT];
        #pragma unroll
        for (int o = 16; o; o >>= 1) {
            d0 += __shfl_xor_sync(0xffffffffu, d0, o);
            d1 += __shfl_xor_sync(0xffffffffu, d1, o);
            d2 += __shfl_xor_sync(0xffffffffu, d2, o);
            d3 += __shfl_xor_sync(0xffffffffu, d3, o);
        }
        if (lane == 0) {
            sm[OFF_DOT + 0 * NW + wrp] = d0;
            sm[OFF_DOT + 1 * NW + wrp] = d1;
            sm[OFF_DOT + 2 * NW + wrp] = d2;
            sm[OFF_DOT + 3 * NW + wrp] = d3;
        }
    }

    int   pbuf = 0;
    int   bprev = -1;
    float rinv_prev = 0.0f;

    while (b < Bn) {
        float* buf = sm + pbuf * BUFSZ;
        float* pbv = sm + (pbuf ^ 1) * BUFSZ;           // prev row's clipped outputs
        const int nbo = (pbuf ^ 1) * BUFSZ;             // prefetch target (same buffer)

        cp_wait_all();            // aw(b) resident
        __syncthreads();          // + dots(b) visible, prev-iter pbv writes done

        if (tid == 0) smi[OFF_B] = atomicAdd(&g_ctr, 1);

        // ---------- prev row: normalize + store burst (drains async under conv) ----------
        if (bprev >= 0) {
            float* outp = out + (size_t)bprev * Tn;
            #pragma unroll
            for (int c = 0; c < 4; c++) {
                const int t0 = c * CHUNK + tid * 4;
                float4 pv = *(const float4*)(&pbv[t0]);
                pv.x *= rinv_prev; pv.y *= rinv_prev;
                pv.z *= rinv_prev; pv.w *= rinv_prev;
                *(float4*)(&outp[t0]) = pv;
            }
        }

        // ---------- warp 0: sigmoid -> 21-tap normalized kernel (staged dots) ----------
        if (wrp == 0) {
            float sv = 0.0f;
            if (lane < 4) {
                #pragma unroll
                for (int i = 0; i < NW; i++) sv += sm[OFF_DOT + lane * NW + i];
                sv += pbias;
                sv = 1.0f / (1.0f + expf(-sv));
            }
            float p0 = __shfl_sync(0xffffffffu, sv, 0);
            float p1 = __shfl_sync(0xffffffffu, sv, 1);
            float p2 = __shfl_sync(0xffffffffu, sv, 2);
            float p3 = __shfl_sync(0xffffffffu, sv, 3);
            float mu  = (float)PAD - p0 * 2.0f;         // 2 * PRIOR_TOKENS_PER_FRAME
            float sg0 = MIN_SIGMA_C + p2;
            float sg1 = sg0 + p3;
            float kv = 0.0f;
            if (lane < FS) {
                float kk = (float)lane;
                float z0 = (kk - mu) / (2.0f * sg0);
                float z1 = (kk - mu) / (2.0f * sg1);
                kv = (1.0f + p1) * (expf(-z0 * z0) / sg0) - p1 * (expf(-z1 * z1) / sg1);
            }
            float ks = kv;
            #pragma unroll
            for (int o = 16; o; o >>= 1) ks += __shfl_xor_sync(0xffffffffu, ks, o);
            if (lane < FS) sm[OFF_KER + lane] = kv / ks;
        }
        __syncthreads();          // ker + bn visible; ALL pbv reads complete
        const int bn = smi[OFF_B];
        const bool pf = (bn < Bn);

        float kr[FS];
        #pragma unroll
        for (int i = 0; i < FS; i++) kr[i] = sm[OFF_KER + i];

        const float* awn  = aw + (size_t)bn * Tn;
        const int4*  mrow = (const int4*)(mask + (size_t)b * Tn);
        float lsum = 0.0f;

        #pragma unroll
        for (int c = 0; c < 4; c++) {
            const int t0 = c * CHUNK + tid * 4;

            // prefetch region c of aw(bn) into pbv (no readers remain -> no race)
            if (pf) {
                cp8(smBase + 4u * (uint32_t)(nbo + PAD + t0),     awn + t0);
                cp8(smBase + 4u * (uint32_t)(nbo + PAD + t0 + 2), awn + t0 + 2);
                cp_commit();
            }
            if (c == 0 && tid < PAD) pbv[tid] = 0.0f;   // re-zero left halo

            // next row's projection dots (L2-hot LDGs hide under conv)
            if (c == 0 && pf) {
                float q0 = query[(size_t)bn * Dn + tid];
                float q1 = query[(size_t)bn * Dn + tid + NT];
                float d0 = q0 * proj_w[0 * Dn + tid] + q1 * proj_w[0 * Dn + tid + NT];
                float d1 = q0 * proj_w[1 * Dn + tid] + q1 * proj_w[1 * Dn + tid + NT];
                float d2 = q0 * proj_w[2 * Dn + tid] + q1 * proj_w[2 * Dn + tid + NT];
                float d3 = q0 * proj_w[3 * Dn + tid] + q1 * proj_w[3 * Dn + tid + NT];
                #pragma unroll
                for (int o = 16; o; o >>= 1) {
                    d0 += __shfl_xor_sync(0xffffffffu, d0, o);
                    d1 += __shfl_xor_sync(0xffffffffu, d1, o);
                    d2 += __shfl_xor_sync(0xffffffffu, d2, o);
                    d3 += __shfl_xor_sync(0xffffffffu, d3, o);
                }
                if (lane == 0) {
                    sm[OFF_DOT + 0 * NW + wrp] = d0;
                    sm[OFF_DOT + 1 * NW + wrp] = d1;
                    sm[OFF_DOT + 2 * NW + wrp] = d2;
                    sm[OFF_DOT + 3 * NW + wrp] = d3;
                }
            }

            int4 mm = mrow[t0 >> 2];                    // mask marshalled as int32

            float w[24];
            #pragma unroll
            for (int j = 0; j < 6; j++) {
                float4 vv = *(const float4*)(&buf[t0 + 4 * j]);
                w[4 * j + 0] = vv.x; w[4 * j + 1] = vv.y;
                w[4 * j + 2] = vv.z; w[4 * j + 3] = vv.w;
            }

            float v[4];
            #pragma unroll
            for (int rr = 0; rr < 4; rr++) {
                float acc = 0.0f;
                #pragma unroll
                for (int i = 0; i < FS; i++) acc = fmaf(w[rr + i], kr[i], acc);
                v[rr] = acc;
            }

            v[0] = fmaxf(mm.x ? v[0] : MASK_VALUE_C, MASK_VALUE_C);
            v[1] = fmaxf(mm.y ? v[1] : MASK_VALUE_C, MASK_VALUE_C);
            v[2] = fmaxf(mm.z ? v[2] : MASK_VALUE_C, MASK_VALUE_C);
            v[3] = fmaxf(mm.w ? v[3] : MASK_VALUE_C, MASK_VALUE_C);
            lsum += v[0] + v[1] + v[2] + v[3];

            __syncthreads();    // all reads of this chunk done before in-place writes
            *(float4*)(&buf[t0]) = make_float4(v[0], v[1], v[2], v[3]);
        }

        // ---------- block-reduce the row sum ----------
        #pragma unroll
        for (int o = 16; o; o >>= 1) lsum += __shfl_xor_sync(0xffffffffu, lsum, o);
        if (lane == 0) sm[OFF_RED + wrp] = lsum;
        __syncthreads();
        if (wrp == 0) {                                  // all 32 lanes participate
            float s = (lane < NW) ? sm[OFF_RED + lane] : 0.0f;
            #pragma unroll
            for (int o = 16; o; o >>= 1) s += __shfl_xor_sync(0xffffffffu, s, o);
            if (lane == 0) sm[OFF_SCL] = s;
        }
        __syncthreads();

        rinv_prev = 1.0f / sm[OFF_SCL];
        bprev = b;
        b = bn;
        pbuf ^= 1;
    }

    // ---------- epilogue: store the final row ----------
    if (bprev >= 0) {
        float* pbv = sm + (pbuf ^ 1) * BUFSZ;
        float* outp = out + (size_t)bprev * Tn;
        #pragma unroll
        for (int c = 0; c < 4; c++) {
            const int t0 = c * CHUNK + tid * 4;
            float4 pv = *(const float4*)(&pbv[t0]);
            pv.x *= rinv_prev; pv.y *= rinv_prev;
            pv.z *= rinv_prev; pv.w *= rinv_prev;
            *(float4*)(&outp[t0]) = pv;
        }
    }
}

extern "C" void kernel_launch(void* const* d_in, const int* in_sizes, int n_in,
                              void* d_out, int out_size)
{
    const float* query  = (const float*)d_in[0];
    const float* aw     = (const float*)d_in[1];
    const int*   mask   = (const int*)d_in[2];
    const float* proj_w = (const float*)d_in[3];
    const float* proj_b = (const float*)d_in[4];
    float*       out    = (float*)d_out;

    cudaFuncSetAttribute(gauss_attn_kernel,
                         cudaFuncAttributeMaxDynamicSharedMemorySize, SM_BYTES);
    reset_ctr_kernel<<<1, 1>>>();
    gauss_attn_kernel<<<GRID, NT, SM_BYTES>>>(query, aw, mask, proj_w, proj_b, out);
}